// round 9
// baseline (speedup 1.0000x reference)
#include <cuda_runtime.h>
#include <cuda_bf16.h>
#include <cstdint>

#define NB 65536   // batch
#define ND 512     // embed dim
#define NP 1024    // prototypes
#define MARGIN 0.08f
#define CAP 16
#define MCTA 64    // query rows per CTA

// Device-global scratch (no runtime allocation allowed)
static __device__ float          g_cnorm[NP * ND];      // normalized centroids fp32
static __device__ __nv_bfloat16  g_cnorm_bf[NP * ND];   // normalized centroids bf16

// Order-preserving float<->uint mapping (for atomicMax on floats)
__device__ __forceinline__ unsigned fmap(float f) {
    unsigned u = __float_as_uint(f);
    return (u & 0x80000000u) ? ~u : (u | 0x80000000u);
}
__device__ __forceinline__ float funmap(unsigned u) {
    u = (u & 0x80000000u) ? (u & 0x7fffffffu) : ~u;
    return __uint_as_float(u);
}

__device__ __forceinline__ uint32_t smem_u32(const void* p) {
    uint32_t a;
    asm("{ .reg .u64 t; cvta.to.shared.u64 t, %1; cvt.u32.u64 %0, t; }"
        : "=r"(a) : "l"(p));
    return a;
}

__device__ __forceinline__ void ldsm_x4(unsigned& r0, unsigned& r1,
                                        unsigned& r2, unsigned& r3, uint32_t addr) {
    asm volatile("ldmatrix.sync.aligned.m8n8.x4.shared.b16 {%0,%1,%2,%3}, [%4];"
                 : "=r"(r0), "=r"(r1), "=r"(r2), "=r"(r3) : "r"(addr));
}

__device__ __forceinline__ void mma16816(float* c, const unsigned* a, const unsigned* b) {
    asm volatile(
        "mma.sync.aligned.m16n8k16.row.col.f32.bf16.bf16.f32 "
        "{%0,%1,%2,%3},{%4,%5,%6,%7},{%8,%9},{%0,%1,%2,%3};\n"
        : "+f"(c[0]), "+f"(c[1]), "+f"(c[2]), "+f"(c[3])
        : "r"(a[0]), "r"(a[1]), "r"(a[2]), "r"(a[3]), "r"(b[0]), "r"(b[1]));
}

// ---------------------------------------------------------------------------
// Kernel 1: L2-normalize centroids -> fp32 + bf16 copies.
// ---------------------------------------------------------------------------
__global__ void normalize_centroids(const float* __restrict__ cent) {
    int row = blockIdx.x;
    int t   = threadIdx.x;  // 0..127
    float4 v = reinterpret_cast<const float4*>(cent + (size_t)row * ND)[t];
    float ss = v.x * v.x + v.y * v.y + v.z * v.z + v.w * v.w;
    #pragma unroll
    for (int o = 16; o > 0; o >>= 1) ss += __shfl_down_sync(0xffffffffu, ss, o);
    __shared__ float sred[4];
    if ((t & 31) == 0) sred[t >> 5] = ss;
    __syncthreads();
    float tot   = sred[0] + sred[1] + sred[2] + sred[3];
    float scale = 1.0f / fmaxf(sqrtf(tot), 1e-12f);
    float4 o4 = make_float4(v.x * scale, v.y * scale, v.z * scale, v.w * scale);
    reinterpret_cast<float4*>(g_cnorm + (size_t)row * ND)[t] = o4;
    __nv_bfloat162 p0 = __floats2bfloat162_rn(o4.x, o4.y);
    __nv_bfloat162 p1 = __floats2bfloat162_rn(o4.z, o4.w);
    uint2 pk = make_uint2(*reinterpret_cast<unsigned*>(&p0),
                          *reinterpret_cast<unsigned*>(&p1));
    reinterpret_cast<uint2*>(g_cnorm_bf)[(size_t)row * (ND / 4) + t] = pk;
}

// ---------------------------------------------------------------------------
// Kernel 2: fused GEMM-argmax. 256 threads (8 warps), CTA owns 64 rows.
// ~106KB smem -> 2 CTAs per SM (32 warps/SM: latency hiding + phase overlap).
//  - warp grid 2M x 4N, warp tile 32x32; group = 2 warps sharing warpN.
//  - A resident in smem bf16 (64 x 512, stride 520), loaded once
//  - per-group B pipeline: 2-slot ring of 32-row x 64-K slices (cp.async),
//    issue-after-barrier schedule, group-local named barrier (64 threads).
//  - lock-free argmax coordination (atomicMax rowMax monotone -> stale read
//    gives candidate superset, still exact), atomicAdd candidate lists.
//  - exact fp32 refinement + fused output writes.
// ---------------------------------------------------------------------------
#define ASTR 520        // bf16 elems per A row (512 + 8 pad)
#define BSTR 72         // bf16 elems per B slice row (64 + 8 pad -> 144B)
#define SLICE_B (32 * BSTR * 2)              // 4608 bytes per slice (32 rows)
#define OFF_STATM 0                          // rowMaxU: 64 u32
#define OFF_CNT   256                        // rowCnt:  64 int
#define OFF_CAND  512                        // cand:    64*CAP ushort (2048B)
#define OFF_A     2560
#define OFF_B     (OFF_A + MCTA * ASTR * 2)  // 69120
#define SMEM_TOTAL (OFF_B + 4 * 2 * SLICE_B) // 105984

__global__ __launch_bounds__(256, 2) void fused_kernel(
    const float* __restrict__ q, const float* __restrict__ cent,
    float* __restrict__ out) {
    extern __shared__ char sm[];
    uint32_t sb = smem_u32(sm);
    unsigned*       rowMaxU = reinterpret_cast<unsigned*>(sm + OFF_STATM);
    int*            rowCnt  = reinterpret_cast<int*>(sm + OFF_CNT);
    unsigned short* cand    = reinterpret_cast<unsigned short*>(sm + OFF_CAND);
    __nv_bfloat16*  sA      = reinterpret_cast<__nv_bfloat16*>(sm + OFF_A);

    const unsigned FULL = 0xffffffffu;
    int tid  = threadIdx.x;
    int lane = tid & 31, wid = tid >> 5;
    int warpM = wid & 1, gid = wid >> 1;     // 2M x 4N grid; group = 2 warps
    int ltid = warpM * 32 + lane;            // thread id within group (0..63)
    int g = lane >> 2, tc = lane & 3;
    int m0 = blockIdx.x * MCTA;
    unsigned barid = gid + 1;

    if (tid < 64) { rowMaxU[tid] = 0u; rowCnt[tid] = 0; }

    // ---- Load resident A tile: 64 x 512 fp32 -> bf16 ----
    const float4* q4 = reinterpret_cast<const float4*>(q);
    #pragma unroll 4
    for (int e = tid; e < MCTA * 128; e += 256) {
        int row = e >> 7, c = e & 127;
        float4 v = q4[(size_t)(m0 + row) * 128 + c];
        __nv_bfloat162 p0 = __floats2bfloat162_rn(v.x, v.y);
        __nv_bfloat162 p1 = __floats2bfloat162_rn(v.z, v.w);
        uint2 pk = make_uint2(*reinterpret_cast<unsigned*>(&p0),
                              *reinterpret_cast<unsigned*>(&p1));
        *reinterpret_cast<uint2*>(&sA[row * ASTR + c * 4]) = pk;
    }

    float acc[2][4][4];
    #pragma unroll
    for (int mt = 0; mt < 2; mt++)
        #pragma unroll
        for (int nt = 0; nt < 4; nt++)
            #pragma unroll
            for (int i = 0; i < 4; i++) acc[mt][nt][i] = 0.0f;

    // Group B pipeline: chunk c = (n-tile c>>3) x (k-chunk c&7).
    // Group slice = 32 centroid rows [ (c>>3)*128 + gid*32, +32 ) x 64 K = 4KB.
    // 64 group threads: each loads 64B (4 x 16B cp.async).
    int brow = ltid >> 1, bq = ltid & 1;
    uint32_t grp_base = sb + OFF_B + gid * (2 * SLICE_B);
    uint32_t dst_base = grp_base + brow * 144 + bq * 64;
    const char* src_base = reinterpret_cast<const char*>(g_cnorm_bf) +
                           (size_t)(gid * 32 + brow) * 1024 + bq * 64;
    auto issue_chunk = [&](int c) {
        uint32_t dst = dst_base + (c & 1) * SLICE_B;
        const char* src = src_base + (size_t)(c >> 3) * 131072 + (c & 7) * 128;
        #pragma unroll
        for (int i = 0; i < 4; i++)
            asm volatile("cp.async.cg.shared.global [%0], [%1], 16;"
                         :: "r"(dst + i * 16), "l"(src + i * 16));
        asm volatile("cp.async.commit_group;" ::: "memory");
    };
    issue_chunk(0);

    // ldmatrix per-lane addresses
    uint32_t aAddr = sb + OFF_A +
        ((warpM * 32 + (lane & 15)) * ASTR + ((lane >> 4) << 3)) * 2;
    uint32_t bLoc =
        ((((lane & 7) + ((lane >> 4) << 3)) * BSTR) + (((lane >> 3) & 1) << 3)) * 2;

    __syncthreads();   // A visible, rowMax/cnt initialized

    // ---- Main loop: 64 chunks = 8 n-tiles x 8 k-chunks of 64 ----
    for (int c = 0; c < 64; c++) {
        asm volatile("cp.async.wait_group 0;" ::: "memory");
        asm volatile("bar.sync %0, %1;" :: "r"(barid), "r"(64) : "memory");
        if (c + 1 < 64) issue_chunk(c + 1);

        uint32_t bufbase = grp_base + (c & 1) * SLICE_B + bLoc;
        int kbase = (c & 7) * 64;

        #pragma unroll
        for (int kk = 0; kk < 64; kk += 16) {
            unsigned a[2][4], b[4][2];
            #pragma unroll
            for (int mt = 0; mt < 2; mt++)
                ldsm_x4(a[mt][0], a[mt][1], a[mt][2], a[mt][3],
                        aAddr + (mt * 16 * ASTR + kbase + kk) * 2);
            #pragma unroll
            for (int p = 0; p < 2; p++) {
                unsigned r0, r1, r2, r3;
                ldsm_x4(r0, r1, r2, r3, bufbase + (p * 16 * BSTR + kk) * 2);
                b[2 * p][0] = r0; b[2 * p][1] = r1;
                b[2 * p + 1][0] = r2; b[2 * p + 1][1] = r3;
            }
            #pragma unroll
            for (int mt = 0; mt < 2; mt++)
                #pragma unroll
                for (int nt = 0; nt < 4; nt++)
                    mma16816(acc[mt][nt], a[mt], b[nt]);
        }

        if ((c & 7) == 7) {   // n-tile finished: group-local argmax epilogue
            int n0 = (c >> 3) * 128 + gid * 32;
            #pragma unroll
            for (int mt = 0; mt < 2; mt++) {
                float v0 = -3.4e38f, v1 = -3.4e38f;
                #pragma unroll
                for (int nt = 0; nt < 4; nt++) {
                    v0 = fmaxf(v0, fmaxf(acc[mt][nt][0], acc[mt][nt][1]));
                    v1 = fmaxf(v1, fmaxf(acc[mt][nt][2], acc[mt][nt][3]));
                }
                v0 = fmaxf(v0, __shfl_xor_sync(FULL, v0, 1));
                v0 = fmaxf(v0, __shfl_xor_sync(FULL, v0, 2));
                v1 = fmaxf(v1, __shfl_xor_sync(FULL, v1, 1));
                v1 = fmaxf(v1, __shfl_xor_sync(FULL, v1, 2));
                if (tc == 0) {
                    int r = warpM * 32 + mt * 16 + g;
                    atomicMax(&rowMaxU[r], fmap(v0));
                    atomicMax(&rowMaxU[r + 8], fmap(v1));
                }
            }
            // group barrier: own maxima published; other groups' arrive
            // opportunistically (stale read -> lower threshold -> candidate
            // superset: still exact).
            asm volatile("bar.sync %0, %1;" :: "r"(barid), "r"(64) : "memory");
            #pragma unroll
            for (int mt = 0; mt < 2; mt++) {
                int r0 = warpM * 32 + mt * 16 + g;
                float th0 = funmap(rowMaxU[r0]) - MARGIN;
                float th1 = funmap(rowMaxU[r0 + 8]) - MARGIN;
                #pragma unroll
                for (int nt = 0; nt < 4; nt++) {
                    #pragma unroll
                    for (int i = 0; i < 4; i++) {
                        float v = acc[mt][nt][i];
                        int   r = (i < 2) ? r0 : r0 + 8;
                        float th = (i < 2) ? th0 : th1;
                        if (v >= th) {
                            int p = atomicAdd(&rowCnt[r], 1);
                            if (p < CAP)
                                cand[r * CAP + p] = (unsigned short)
                                    (n0 + nt * 8 + tc * 2 + (i & 1));
                        }
                        acc[mt][nt][i] = 0.0f;
                    }
                }
            }
        }
    }
    __syncthreads();   // all groups done: candidates complete

    // ---- Refinement + output writes: warp w owns rows [w*8, w*8+8) ----
    const float4* c4n = reinterpret_cast<const float4*>(g_cnorm);
    const float4* ce4 = reinterpret_cast<const float4*>(cent);
    float* outHard = out + (size_t)NB * ND;
    float* outOH   = outHard + NB;

    for (int rr = 0; rr < 8; rr++) {
        int r = wid * 8 + rr;
        int b = m0 + r;
        int cnt = rowCnt[r];
        int winner;
        if (cnt == 1) {
            winner = cand[r * CAP];
        } else {
            // exact fp32 dots; q row cached in registers
            float4 aq[4];
            const float4* qr = q4 + (size_t)b * 128;
            #pragma unroll
            for (int i = 0; i < 4; i++) aq[i] = qr[lane + 32 * i];
            float bv = -3.4e38f; int bi = NP;
            int lim = (cnt <= CAP) ? cnt : NP;   // overflow -> full exact scan
            for (int j = 0; j < lim; j++) {
                int col = (cnt <= CAP) ? (int)cand[r * CAP + j] : j;
                const float4* cr = c4n + (size_t)col * 128;
                float s = 0.0f;
                #pragma unroll
                for (int i = 0; i < 4; i++) {
                    float4 cc = cr[lane + 32 * i];
                    s = fmaf(aq[i].x, cc.x, fmaf(aq[i].y, cc.y,
                        fmaf(aq[i].z, cc.z, fmaf(aq[i].w, cc.w, s))));
                }
                #pragma unroll
                for (int o = 16; o > 0; o >>= 1)
                    s += __shfl_xor_sync(FULL, s, o);
                if (s > bv || (s == bv && col < bi)) { bv = s; bi = col; }
            }
            winner = bi;
        }

        // context gather (raw centroids)
        float4* ctx = reinterpret_cast<float4*>(out + (size_t)b * ND);
        #pragma unroll
        for (int i = 0; i < 4; i++)
            ctx[lane + 32 * i] = ce4[(size_t)winner * 128 + lane + 32 * i];
        if (lane == 0) outHard[b] = (float)winner;
        // full one-hot row (zeros + 1.0)
        float4* oh = reinterpret_cast<float4*>(outOH + (size_t)b * NP);
        int wq = winner >> 2, wr = winner & 3;
        #pragma unroll
        for (int i = 0; i < 8; i++) {
            int j = lane + 32 * i;
            float4 z = make_float4(0.f, 0.f, 0.f, 0.f);
            if (j == wq) reinterpret_cast<float*>(&z)[wr] = 1.0f;
            oh[j] = z;
        }
    }
}

// ---------------------------------------------------------------------------
// Launch: out = [context (B*D) | hard (B) | routing (B*P)] as float32
// ---------------------------------------------------------------------------
extern "C" void kernel_launch(void* const* d_in, const int* in_sizes, int n_in,
                              void* d_out, int out_size) {
    const float* q    = (const float*)d_in[0];  // (B, D) fp32
    const float* cent = (const float*)d_in[1];  // (P, D) fp32
    float* out = (float*)d_out;

    cudaFuncSetAttribute(fused_kernel,
                         cudaFuncAttributeMaxDynamicSharedMemorySize, SMEM_TOTAL);
    normalize_centroids<<<NP, 128>>>(cent);
    fused_kernel<<<NB / MCTA, 256, SMEM_TOTAL>>>(q, cent, out);
}

// round 11
// speedup vs baseline: 1.0317x; 1.0317x over previous
#include <cuda_runtime.h>
#include <cuda_bf16.h>
#include <cstdint>

#define NB 65536   // batch
#define ND 512     // embed dim
#define NP 1024    // prototypes
#define MARGIN 0.08f
#define CAP 16
#define MCTA 64    // query rows per CTA

// Device-global scratch (no runtime allocation allowed)
static __device__ float          g_cnorm[NP * ND];      // normalized centroids fp32
static __device__ __nv_bfloat16  g_cnorm_bf[NP * ND];   // normalized centroids bf16
static __device__ __nv_bfloat16  g_q_bf[(size_t)NB * ND];  // queries bf16 (64 MB)

// Order-preserving float<->uint mapping (for atomicMax on floats)
__device__ __forceinline__ unsigned fmap(float f) {
    unsigned u = __float_as_uint(f);
    return (u & 0x80000000u) ? ~u : (u | 0x80000000u);
}
__device__ __forceinline__ float funmap(unsigned u) {
    u = (u & 0x80000000u) ? (u & 0x7fffffffu) : ~u;
    return __uint_as_float(u);
}

__device__ __forceinline__ uint32_t smem_u32(const void* p) {
    uint32_t a;
    asm("{ .reg .u64 t; cvta.to.shared.u64 t, %1; cvt.u32.u64 %0, t; }"
        : "=r"(a) : "l"(p));
    return a;
}

__device__ __forceinline__ void ldsm_x4(unsigned& r0, unsigned& r1,
                                        unsigned& r2, unsigned& r3, uint32_t addr) {
    asm volatile("ldmatrix.sync.aligned.m8n8.x4.shared.b16 {%0,%1,%2,%3}, [%4];"
                 : "=r"(r0), "=r"(r1), "=r"(r2), "=r"(r3) : "r"(addr));
}

__device__ __forceinline__ void mma16816(float* c, const unsigned* a, const unsigned* b) {
    asm volatile(
        "mma.sync.aligned.m16n8k16.row.col.f32.bf16.bf16.f32 "
        "{%0,%1,%2,%3},{%4,%5,%6,%7},{%8,%9},{%0,%1,%2,%3};\n"
        : "+f"(c[0]), "+f"(c[1]), "+f"(c[2]), "+f"(c[3])
        : "r"(a[0]), "r"(a[1]), "r"(a[2]), "r"(a[3]), "r"(b[0]), "r"(b[1]));
}

// ---------------------------------------------------------------------------
// Kernel 0: convert q to bf16 (g_q_bf).
// ---------------------------------------------------------------------------
__global__ void convert_q(const float* __restrict__ q) {
    const float4* q4 = reinterpret_cast<const float4*>(q);
    uint2* dst = reinterpret_cast<uint2*>(g_q_bf);
    size_t i0 = (size_t)(blockIdx.x * blockDim.x + threadIdx.x) * 4;
    #pragma unroll
    for (int j = 0; j < 4; j++) {
        float4 v = q4[i0 + j];
        __nv_bfloat162 p0 = __floats2bfloat162_rn(v.x, v.y);
        __nv_bfloat162 p1 = __floats2bfloat162_rn(v.z, v.w);
        dst[i0 + j] = make_uint2(*reinterpret_cast<unsigned*>(&p0),
                                 *reinterpret_cast<unsigned*>(&p1));
    }
}

// ---------------------------------------------------------------------------
// Kernel 1: L2-normalize centroids -> fp32 + bf16 copies.
// ---------------------------------------------------------------------------
__global__ void normalize_centroids(const float* __restrict__ cent) {
    int row = blockIdx.x;
    int t   = threadIdx.x;  // 0..127
    float4 v = reinterpret_cast<const float4*>(cent + (size_t)row * ND)[t];
    float ss = v.x * v.x + v.y * v.y + v.z * v.z + v.w * v.w;
    #pragma unroll
    for (int o = 16; o > 0; o >>= 1) ss += __shfl_down_sync(0xffffffffu, ss, o);
    __shared__ float sred[4];
    if ((t & 31) == 0) sred[t >> 5] = ss;
    __syncthreads();
    float tot   = sred[0] + sred[1] + sred[2] + sred[3];
    float scale = 1.0f / fmaxf(sqrtf(tot), 1e-12f);
    float4 o4 = make_float4(v.x * scale, v.y * scale, v.z * scale, v.w * scale);
    reinterpret_cast<float4*>(g_cnorm + (size_t)row * ND)[t] = o4;
    __nv_bfloat162 p0 = __floats2bfloat162_rn(o4.x, o4.y);
    __nv_bfloat162 p1 = __floats2bfloat162_rn(o4.z, o4.w);
    uint2 pk = make_uint2(*reinterpret_cast<unsigned*>(&p0),
                          *reinterpret_cast<unsigned*>(&p1));
    reinterpret_cast<uint2*>(g_cnorm_bf)[(size_t)row * (ND / 4) + t] = pk;
}

// ---------------------------------------------------------------------------
// Kernel 2: fused GEMM-argmax. 512 threads (16 warps), CTA owns 64 rows.
// ~57KB smem + <=64 regs -> 2 CTAs/SM (32 warps): cross-CTA phase overlap.
//  - warp grid 4M x 4N, warp tile 16x32; covers 64M x 128N per n-tile.
//  - A and B streamed in 64-K double-buffered chunks (cp.async).
//  - per-n-tile running max + margin candidates, exact fp32 refinement,
//    fused output writes (context gather, hard index, full one-hot).
// ---------------------------------------------------------------------------
#define CSTR 72         // bf16 elems per chunk row (64 + 8 pad -> 144B)
#define ACHUNK (MCTA * 144)                  // 9216 bytes
#define BCHUNK (128 * 144)                   // 18432 bytes
#define OFF_STATM 0                          // rowMaxU: 64 u32 (256B)
#define OFF_CNT   256                        // rowCnt:  64 int (256B)
#define OFF_CAND  512                        // cand:    64*CAP ushort (2048B)
#define OFF_A     2560
#define OFF_BB    (OFF_A + 2 * ACHUNK)       // 20992
#define SMEM_TOTAL (OFF_BB + 2 * BCHUNK)     // 57856

__global__ __launch_bounds__(512, 2) void fused_kernel(
    const float* __restrict__ q, const float* __restrict__ cent,
    float* __restrict__ out) {
    extern __shared__ char sm[];
    uint32_t sb = smem_u32(sm);
    unsigned*       rowMaxU = reinterpret_cast<unsigned*>(sm + OFF_STATM);
    int*            rowCnt  = reinterpret_cast<int*>(sm + OFF_CNT);
    unsigned short* cand    = reinterpret_cast<unsigned short*>(sm + OFF_CAND);

    const unsigned FULL = 0xffffffffu;
    int tid  = threadIdx.x;
    int lane = tid & 31, wid = tid >> 5;
    int warpM = wid & 3, warpN = wid >> 2;   // 4M x 4N grid, warp tile 16x32
    int g = lane >> 2, tc = lane & 3;
    int m0 = blockIdx.x * MCTA;

    if (tid < MCTA) { rowMaxU[tid] = 0u; rowCnt[tid] = 0; }

    float acc[4][4];
    #pragma unroll
    for (int nt = 0; nt < 4; nt++)
        #pragma unroll
        for (int i = 0; i < 4; i++) acc[nt][i] = 0.0f;

    // Chunk loaders: chunk c = (n-tile c>>3) x (k-chunk c&7).
    // A: 64 rows x 128B = 8KB -> 512 threads x 1 cp.async 16B.
    // B: 128 rows x 128B = 16KB -> 512 threads x 2 cp.async 16B.
    int rowA = tid >> 3, lqA = (tid & 7) * 16;
    int rowB = tid >> 2, lqB = (tid & 3) * 32;
    uint32_t dstA = sb + OFF_A  + rowA * 144 + lqA;
    uint32_t dstB = sb + OFF_BB + rowB * 144 + lqB;
    const char* srcA0 = reinterpret_cast<const char*>(g_q_bf) +
                        (size_t)(m0 + rowA) * 1024 + lqA;
    const char* srcB0 = reinterpret_cast<const char*>(g_cnorm_bf) +
                        (size_t)rowB * 1024 + lqB;
    auto issue_chunk = [&](int c) {
        int slot = c & 1, kc = c & 7, nt = c >> 3;
        uint32_t dA = dstA + slot * ACHUNK;
        uint32_t dB = dstB + slot * BCHUNK;
        const char* sA = srcA0 + kc * 128;
        const char* sB = srcB0 + (size_t)nt * 131072 + kc * 128;
        asm volatile("cp.async.cg.shared.global [%0], [%1], 16;" :: "r"(dA), "l"(sA));
        asm volatile("cp.async.cg.shared.global [%0], [%1], 16;" :: "r"(dB), "l"(sB));
        asm volatile("cp.async.cg.shared.global [%0], [%1], 16;" :: "r"(dB + 16), "l"(sB + 16));
        asm volatile("cp.async.commit_group;" ::: "memory");
    };
    issue_chunk(0);

    // ldmatrix per-lane address components (within a chunk buffer)
    uint32_t aLoc = ((warpM * 16 + (lane & 15)) * CSTR + ((lane >> 4) << 3)) * 2;
    uint32_t bLoc = ((warpN * 32 + (lane & 7) + ((lane >> 4) << 3)) * CSTR +
                     (((lane >> 3) & 1) << 3)) * 2;

    __syncthreads();   // rowMax/cnt initialized

    // ---- Main loop: 64 chunks = 8 n-tiles x 8 k-chunks of 64 ----
    for (int c = 0; c < 64; c++) {
        asm volatile("cp.async.wait_group 0;" ::: "memory");
        __syncthreads();
        if (c + 1 < 64) issue_chunk(c + 1);

        uint32_t aBase = sb + OFF_A  + (c & 1) * ACHUNK + aLoc;
        uint32_t bBase = sb + OFF_BB + (c & 1) * BCHUNK + bLoc;

        #pragma unroll
        for (int kk = 0; kk < 64; kk += 16) {
            unsigned a[4], b[4][2];
            ldsm_x4(a[0], a[1], a[2], a[3], aBase + kk * 2);
            #pragma unroll
            for (int p = 0; p < 2; p++) {
                unsigned r0, r1, r2, r3;
                ldsm_x4(r0, r1, r2, r3, bBase + (p * 16 * CSTR + kk) * 2);
                b[2 * p][0] = r0; b[2 * p][1] = r1;
                b[2 * p + 1][0] = r2; b[2 * p + 1][1] = r3;
            }
            #pragma unroll
            for (int nt = 0; nt < 4; nt++)
                mma16816(acc[nt], a, b[nt]);
        }

        if ((c & 7) == 7) {   // n-tile finished: argmax epilogue
            int n0 = (c >> 3) * 128;
            float v0 = -3.4e38f, v1 = -3.4e38f;
            #pragma unroll
            for (int nt = 0; nt < 4; nt++) {
                v0 = fmaxf(v0, fmaxf(acc[nt][0], acc[nt][1]));
                v1 = fmaxf(v1, fmaxf(acc[nt][2], acc[nt][3]));
            }
            v0 = fmaxf(v0, __shfl_xor_sync(FULL, v0, 1));
            v0 = fmaxf(v0, __shfl_xor_sync(FULL, v0, 2));
            v1 = fmaxf(v1, __shfl_xor_sync(FULL, v1, 1));
            v1 = fmaxf(v1, __shfl_xor_sync(FULL, v1, 2));
            int r = warpM * 16 + g;
            if (tc == 0) {
                atomicMax(&rowMaxU[r], fmap(v0));
                atomicMax(&rowMaxU[r + 8], fmap(v1));
            }
            __syncthreads();
            float th0 = funmap(rowMaxU[r]) - MARGIN;
            float th1 = funmap(rowMaxU[r + 8]) - MARGIN;
            #pragma unroll
            for (int nt = 0; nt < 4; nt++) {
                #pragma unroll
                for (int i = 0; i < 4; i++) {
                    float v = acc[nt][i];
                    int   rr = (i < 2) ? r : r + 8;
                    float th = (i < 2) ? th0 : th1;
                    if (v >= th) {
                        int p = atomicAdd(&rowCnt[rr], 1);
                        if (p < CAP)
                            cand[rr * CAP + p] = (unsigned short)
                                (n0 + warpN * 32 + nt * 8 + tc * 2 + (i & 1));
                    }
                    acc[nt][i] = 0.0f;
                }
            }
        }
    }
    __syncthreads();   // candidates complete

    // ---- Refinement + output writes: warp w owns rows [w*4, w*4+4) ----
    const float4* q4  = reinterpret_cast<const float4*>(q);
    const float4* c4n = reinterpret_cast<const float4*>(g_cnorm);
    const float4* ce4 = reinterpret_cast<const float4*>(cent);
    float* outHard = out + (size_t)NB * ND;
    float* outOH   = outHard + NB;

    for (int rr = 0; rr < 4; rr++) {
        int r = wid * 4 + rr;
        int b = m0 + r;
        int cnt = rowCnt[r];
        int winner;
        if (cnt == 1) {
            winner = cand[r * CAP];
        } else {
            // exact fp32 dots; q row cached in registers
            float4 aq[4];
            const float4* qr = q4 + (size_t)b * 128;
            #pragma unroll
            for (int i = 0; i < 4; i++) aq[i] = qr[lane + 32 * i];
            float bv = -3.4e38f; int bi = NP;
            int lim = (cnt <= CAP) ? cnt : NP;   // overflow -> full exact scan
            for (int j = 0; j < lim; j++) {
                int col = (cnt <= CAP) ? (int)cand[r * CAP + j] : j;
                const float4* cr = c4n + (size_t)col * 128;
                float s = 0.0f;
                #pragma unroll
                for (int i = 0; i < 4; i++) {
                    float4 cc = cr[lane + 32 * i];
                    s = fmaf(aq[i].x, cc.x, fmaf(aq[i].y, cc.y,
                        fmaf(aq[i].z, cc.z, fmaf(aq[i].w, cc.w, s))));
                }
                #pragma unroll
                for (int o = 16; o > 0; o >>= 1)
                    s += __shfl_xor_sync(FULL, s, o);
                if (s > bv || (s == bv && col < bi)) { bv = s; bi = col; }
            }
            winner = bi;
        }

        // context gather (raw centroids)
        float4* ctx = reinterpret_cast<float4*>(out + (size_t)b * ND);
        #pragma unroll
        for (int i = 0; i < 4; i++)
            ctx[lane + 32 * i] = ce4[(size_t)winner * 128 + lane + 32 * i];
        if (lane == 0) outHard[b] = (float)winner;
        // full one-hot row (zeros + 1.0)
        float4* oh = reinterpret_cast<float4*>(outOH + (size_t)b * NP);
        int wq = winner >> 2, wr = winner & 3;
        #pragma unroll
        for (int i = 0; i < 8; i++) {
            int j = lane + 32 * i;
            float4 z = make_float4(0.f, 0.f, 0.f, 0.f);
            if (j == wq) reinterpret_cast<float*>(&z)[wr] = 1.0f;
            oh[j] = z;
        }
    }
}

// ---------------------------------------------------------------------------
// Launch: out = [context (B*D) | hard (B) | routing (B*P)] as float32
// ---------------------------------------------------------------------------
extern "C" void kernel_launch(void* const* d_in, const int* in_sizes, int n_in,
                              void* d_out, int out_size) {
    const float* q    = (const float*)d_in[0];  // (B, D) fp32
    const float* cent = (const float*)d_in[1];  // (P, D) fp32
    float* out = (float*)d_out;

    cudaFuncSetAttribute(fused_kernel,
                         cudaFuncAttributeMaxDynamicSharedMemorySize, SMEM_TOTAL);
    convert_q<<<NB * ND / (4 * 4 * 256), 256>>>(q);
    normalize_centroids<<<NP, 128>>>(cent);
    fused_kernel<<<NB / MCTA, 512, SMEM_TOTAL>>>(q, cent, out);
}

// round 12
// speedup vs baseline: 1.2631x; 1.2243x over previous
#include <cuda_runtime.h>
#include <cuda_bf16.h>
#include <cstdint>

#define NB 65536   // batch
#define ND 512     // embed dim
#define NP 1024    // prototypes
#define MARGIN 0.08f
#define CAP 16

// Device-global scratch (no runtime allocation allowed)
static __device__ float          g_cnorm[NP * ND];      // normalized centroids fp32
static __device__ __nv_bfloat16  g_cnorm_bf[NP * ND];   // normalized centroids bf16
static __device__ uint2          g_bfrag[128 * 32 * 32];// [colblk][kk16][lane] frag records

// Order-preserving float<->uint mapping (for atomicMax on floats)
__device__ __forceinline__ unsigned fmap(float f) {
    unsigned u = __float_as_uint(f);
    return (u & 0x80000000u) ? ~u : (u | 0x80000000u);
}
__device__ __forceinline__ float funmap(unsigned u) {
    u = (u & 0x80000000u) ? (u & 0x7fffffffu) : ~u;
    return __uint_as_float(u);
}

__device__ __forceinline__ uint32_t smem_u32(const void* p) {
    uint32_t a;
    asm("{ .reg .u64 t; cvta.to.shared.u64 t, %1; cvt.u32.u64 %0, t; }"
        : "=r"(a) : "l"(p));
    return a;
}

__device__ __forceinline__ void ldsm_x4(unsigned& r0, unsigned& r1,
                                        unsigned& r2, unsigned& r3, uint32_t addr) {
    asm volatile("ldmatrix.sync.aligned.m8n8.x4.shared.b16 {%0,%1,%2,%3}, [%4];"
                 : "=r"(r0), "=r"(r1), "=r"(r2), "=r"(r3) : "r"(addr));
}

__device__ __forceinline__ void mma16816(float* c, const unsigned* a, const unsigned* b) {
    asm volatile(
        "mma.sync.aligned.m16n8k16.row.col.f32.bf16.bf16.f32 "
        "{%0,%1,%2,%3},{%4,%5,%6,%7},{%8,%9},{%0,%1,%2,%3};\n"
        : "+f"(c[0]), "+f"(c[1]), "+f"(c[2]), "+f"(c[3])
        : "r"(a[0]), "r"(a[1]), "r"(a[2]), "r"(a[3]), "r"(b[0]), "r"(b[1]));
}

// ---------------------------------------------------------------------------
// Kernel 1: L2-normalize centroids -> fp32 + bf16 copies.
// ---------------------------------------------------------------------------
__global__ void normalize_centroids(const float* __restrict__ cent) {
    int row = blockIdx.x;
    int t   = threadIdx.x;  // 0..127
    float4 v = reinterpret_cast<const float4*>(cent + (size_t)row * ND)[t];
    float ss = v.x * v.x + v.y * v.y + v.z * v.z + v.w * v.w;
    #pragma unroll
    for (int o = 16; o > 0; o >>= 1) ss += __shfl_down_sync(0xffffffffu, ss, o);
    __shared__ float sred[4];
    if ((t & 31) == 0) sred[t >> 5] = ss;
    __syncthreads();
    float tot   = sred[0] + sred[1] + sred[2] + sred[3];
    float scale = 1.0f / fmaxf(sqrtf(tot), 1e-12f);
    float4 o4 = make_float4(v.x * scale, v.y * scale, v.z * scale, v.w * scale);
    reinterpret_cast<float4*>(g_cnorm + (size_t)row * ND)[t] = o4;
    __nv_bfloat162 p0 = __floats2bfloat162_rn(o4.x, o4.y);
    __nv_bfloat162 p1 = __floats2bfloat162_rn(o4.z, o4.w);
    uint2 pk = make_uint2(*reinterpret_cast<unsigned*>(&p0),
                          *reinterpret_cast<unsigned*>(&p1));
    reinterpret_cast<uint2*>(g_cnorm_bf)[(size_t)row * (ND / 4) + t] = pk;
}

// ---------------------------------------------------------------------------
// Kernel 1b: build fragment-native B layout.
// Record r = (colblk cb, k-chunk kki): 32 lanes x uint2 where lane l
// (g=l>>2, tc=l&3) holds {B[cb*8+g][kk+tc*2 pair], B[cb*8+g][kk+8+tc*2 pair]}.
// A consuming warp does ONE coalesced 256B LDG.64 per 8-col fragment.
// ---------------------------------------------------------------------------
__global__ void build_bfrag() {
    int r    = blockIdx.x * 8 + (threadIdx.x >> 5);  // record id 0..4095
    int lane = threadIdx.x & 31;
    int cb = r >> 5, kk = (r & 31) * 16;
    int n  = cb * 8 + (lane >> 2);
    int k0 = kk + (lane & 3) * 2;
    const unsigned* src = reinterpret_cast<const unsigned*>(g_cnorm_bf);
    unsigned x = src[(n * ND + k0) >> 1];
    unsigned y = src[(n * ND + k0 + 8) >> 1];
    g_bfrag[r * 32 + lane] = make_uint2(x, y);
}

// ---------------------------------------------------------------------------
// Kernel 2: fused GEMM-argmax. 512 threads (16 warps), CTA owns 128 rows.
//  - warp grid 4M x 4N, warp tile 32x32
//  - A resident in smem bf16 (128 x 512, stride 520): LDSM, read-only
//  - B fetched per-fragment from g_bfrag via coalesced LDG.64 into registers,
//    depth-2 rotating prefetch. NO smem B, NO cp.async, NO mainloop barriers.
//  - per-n-tile epilogue (8 total): atomicMax rowMax + margin candidates
//    (monotone -> stale reads give candidate superset: still exact).
//  - exact fp32 refinement + fused output writes.
// ---------------------------------------------------------------------------
#define ASTR 520        // bf16 elems per A row (512 + 8 pad)
#define OFF_STATM 0                          // rowMaxU: 128 u32
#define OFF_CNT   512                        // rowCnt:  128 int
#define OFF_CAND  1024                       // cand:    128*CAP ushort (4096B)
#define OFF_A     5120
#define SMEM_TOTAL (OFF_A + 128 * ASTR * 2)  // 138240

__global__ __launch_bounds__(512, 1) void fused_kernel(
    const float* __restrict__ q, const float* __restrict__ cent,
    float* __restrict__ out) {
    extern __shared__ char sm[];
    uint32_t sb = smem_u32(sm);
    unsigned*       rowMaxU = reinterpret_cast<unsigned*>(sm + OFF_STATM);
    int*            rowCnt  = reinterpret_cast<int*>(sm + OFF_CNT);
    unsigned short* cand    = reinterpret_cast<unsigned short*>(sm + OFF_CAND);
    __nv_bfloat16*  sA      = reinterpret_cast<__nv_bfloat16*>(sm + OFF_A);

    const unsigned FULL = 0xffffffffu;
    int tid  = threadIdx.x;
    int lane = tid & 31, wid = tid >> 5;
    int warpM = wid & 3, warpN = wid >> 2;   // 4M x 4N grid, warp tile 32x32
    int g = lane >> 2, tc = lane & 3;
    int m0 = blockIdx.x * 128;

    if (tid < 128) { rowMaxU[tid] = 0u; rowCnt[tid] = 0; }

    // ---- Load resident A tile: 128 x 512 fp32 -> bf16 ----
    const float4* q4 = reinterpret_cast<const float4*>(q);
    #pragma unroll 4
    for (int e = tid; e < 128 * 128; e += 512) {
        int row = e >> 7, c = e & 127;
        float4 v = q4[(size_t)(m0 + row) * 128 + c];
        __nv_bfloat162 p0 = __floats2bfloat162_rn(v.x, v.y);
        __nv_bfloat162 p1 = __floats2bfloat162_rn(v.z, v.w);
        uint2 pk = make_uint2(*reinterpret_cast<unsigned*>(&p0),
                              *reinterpret_cast<unsigned*>(&p1));
        *reinterpret_cast<uint2*>(&sA[row * ASTR + c * 4]) = pk;
    }

    float acc[2][4][4];
    #pragma unroll
    for (int mt = 0; mt < 2; mt++)
        #pragma unroll
        for (int s = 0; s < 4; s++)
            #pragma unroll
            for (int i = 0; i < 4; i++) acc[mt][s][i] = 0.0f;

    // B fragment base: warp's 4 col-subtiles = records
    //   ((c>>5)*16 + warpN*4 + s)*32 + (c&31), lane-indexed uint2.
    const uint2* bbase = g_bfrag + warpN * 4096 + lane;
    unsigned b[4][4][2];   // [slot][subtile][frag]
    auto loadB = [&](int slot, int cc) {
        int off = (cc >> 5) * 16384 + (cc & 31) * 32;
        #pragma unroll
        for (int s = 0; s < 4; s++) {
            uint2 v = __ldg(bbase + off + s * 1024);
            b[slot][s][0] = v.x; b[slot][s][1] = v.y;
        }
    };
    loadB(0, 0);
    loadB(1, 1);

    uint32_t aAddr = sb + OFF_A +
        ((warpM * 32 + (lane & 15)) * ASTR + ((lane >> 4) << 3)) * 2;

    __syncthreads();   // A visible, rowMax/cnt initialized

    // ---- Main loop: 256 steps = 8 n-tiles x 32 k-steps of 16. No barriers
    //      except one __syncthreads inside each of the 8 epilogues. ----
    #pragma unroll 8
    for (int c = 0; c < 256; c++) {
        if (c + 2 < 256) loadB((c + 2) & 3, c + 2);

        int kb = (c & 31) * 16;
        unsigned a[2][4];
        #pragma unroll
        for (int mt = 0; mt < 2; mt++)
            ldsm_x4(a[mt][0], a[mt][1], a[mt][2], a[mt][3],
                    aAddr + (mt * 16 * ASTR + kb) * 2);
        int sl = c & 3;
        #pragma unroll
        for (int mt = 0; mt < 2; mt++)
            #pragma unroll
            for (int s = 0; s < 4; s++)
                mma16816(acc[mt][s], a[mt], b[sl][s]);

        if ((c & 31) == 31) {   // n-tile finished: argmax epilogue
            int n0 = (c >> 5) * 128;
            #pragma unroll
            for (int mt = 0; mt < 2; mt++) {
                float v0 = -3.4e38f, v1 = -3.4e38f;
                #pragma unroll
                for (int s = 0; s < 4; s++) {
                    v0 = fmaxf(v0, fmaxf(acc[mt][s][0], acc[mt][s][1]));
                    v1 = fmaxf(v1, fmaxf(acc[mt][s][2], acc[mt][s][3]));
                }
                v0 = fmaxf(v0, __shfl_xor_sync(FULL, v0, 1));
                v0 = fmaxf(v0, __shfl_xor_sync(FULL, v0, 2));
                v1 = fmaxf(v1, __shfl_xor_sync(FULL, v1, 1));
                v1 = fmaxf(v1, __shfl_xor_sync(FULL, v1, 2));
                if (tc == 0) {
                    int r = warpM * 32 + mt * 16 + g;
                    atomicMax(&rowMaxU[r], fmap(v0));
                    atomicMax(&rowMaxU[r + 8], fmap(v1));
                }
            }
            __syncthreads();   // all maxima for this tile published
            #pragma unroll
            for (int mt = 0; mt < 2; mt++) {
                int r0 = warpM * 32 + mt * 16 + g;
                float th0 = funmap(rowMaxU[r0]) - MARGIN;
                float th1 = funmap(rowMaxU[r0 + 8]) - MARGIN;
                #pragma unroll
                for (int s = 0; s < 4; s++) {
                    #pragma unroll
                    for (int i = 0; i < 4; i++) {
                        float v = acc[mt][s][i];
                        int   r = (i < 2) ? r0 : r0 + 8;
                        float th = (i < 2) ? th0 : th1;
                        if (v >= th) {
                            int p = atomicAdd(&rowCnt[r], 1);
                            if (p < CAP)
                                cand[r * CAP + p] = (unsigned short)
                                    (n0 + warpN * 32 + s * 8 + tc * 2 + (i & 1));
                        }
                        acc[mt][s][i] = 0.0f;
                    }
                }
            }
        }
    }
    __syncthreads();   // candidates complete

    // ---- Refinement + output writes: warp w owns rows [w*8, w*8+8) ----
    const float4* c4n = reinterpret_cast<const float4*>(g_cnorm);
    const float4* ce4 = reinterpret_cast<const float4*>(cent);
    float* outHard = out + (size_t)NB * ND;
    float* outOH   = outHard + NB;

    for (int rr = 0; rr < 8; rr++) {
        int r = wid * 8 + rr;
        int b2 = m0 + r;
        int cnt = rowCnt[r];
        int winner;
        if (cnt == 1) {
            winner = cand[r * CAP];
        } else {
            // exact fp32 dots; q row cached in registers
            float4 aq[4];
            const float4* qr = q4 + (size_t)b2 * 128;
            #pragma unroll
            for (int i = 0; i < 4; i++) aq[i] = qr[lane + 32 * i];
            float bv = -3.4e38f; int bi = NP;
            int lim = (cnt <= CAP) ? cnt : NP;   // overflow -> full exact scan
            for (int j = 0; j < lim; j++) {
                int col = (cnt <= CAP) ? (int)cand[r * CAP + j] : j;
                const float4* cr = c4n + (size_t)col * 128;
                float s = 0.0f;
                #pragma unroll
                for (int i = 0; i < 4; i++) {
                    float4 cc = cr[lane + 32 * i];
                    s = fmaf(aq[i].x, cc.x, fmaf(aq[i].y, cc.y,
                        fmaf(aq[i].z, cc.z, fmaf(aq[i].w, cc.w, s))));
                }
                #pragma unroll
                for (int o = 16; o > 0; o >>= 1)
                    s += __shfl_xor_sync(FULL, s, o);
                if (s > bv || (s == bv && col < bi)) { bv = s; bi = col; }
            }
            winner = bi;
        }

        // context gather (raw centroids)
        float4* ctx = reinterpret_cast<float4*>(out + (size_t)b2 * ND);
        #pragma unroll
        for (int i = 0; i < 4; i++)
            ctx[lane + 32 * i] = ce4[(size_t)winner * 128 + lane + 32 * i];
        if (lane == 0) outHard[b2] = (float)winner;
        // full one-hot row (zeros + 1.0)
        float4* oh = reinterpret_cast<float4*>(outOH + (size_t)b2 * NP);
        int wq = winner >> 2, wr = winner & 3;
        #pragma unroll
        for (int i = 0; i < 8; i++) {
            int j = lane + 32 * i;
            float4 z = make_float4(0.f, 0.f, 0.f, 0.f);
            if (j == wq) reinterpret_cast<float*>(&z)[wr] = 1.0f;
            oh[j] = z;
        }
    }
}

// ---------------------------------------------------------------------------
// Launch: out = [context (B*D) | hard (B) | routing (B*P)] as float32
// ---------------------------------------------------------------------------
extern "C" void kernel_launch(void* const* d_in, const int* in_sizes, int n_in,
                              void* d_out, int out_size) {
    const float* q    = (const float*)d_in[0];  // (B, D) fp32
    const float* cent = (const float*)d_in[1];  // (P, D) fp32
    float* out = (float*)d_out;

    cudaFuncSetAttribute(fused_kernel,
                         cudaFuncAttributeMaxDynamicSharedMemorySize, SMEM_TOTAL);
    normalize_centroids<<<NP, 128>>>(cent);
    build_bfrag<<<512, 256>>>();
    fused_kernel<<<NB / 128, 512, SMEM_TOTAL>>>(q, cent, out);
}

// round 13
// speedup vs baseline: 1.3199x; 1.0449x over previous
#include <cuda_runtime.h>
#include <cuda_bf16.h>
#include <cstdint>

#define NB 65536   // batch
#define ND 512     // embed dim
#define NP 1024    // prototypes
#define MARGIN 0.08f
#define CAP 16

// Device-global scratch (no runtime allocation allowed)
static __device__ float          g_cnorm[NP * ND];      // normalized centroids fp32
static __device__ __nv_bfloat16  g_cnorm_bf[NP * ND];   // normalized centroids bf16
static __device__ uint2          g_bfrag[128 * 32 * 32];// [colblk][kk16][lane] frag records

// Order-preserving float<->uint mapping (for atomicMax on floats)
__device__ __forceinline__ unsigned fmap(float f) {
    unsigned u = __float_as_uint(f);
    return (u & 0x80000000u) ? ~u : (u | 0x80000000u);
}
__device__ __forceinline__ float funmap(unsigned u) {
    u = (u & 0x80000000u) ? (u & 0x7fffffffu) : ~u;
    return __uint_as_float(u);
}

__device__ __forceinline__ uint32_t smem_u32(const void* p) {
    uint32_t a;
    asm("{ .reg .u64 t; cvta.to.shared.u64 t, %1; cvt.u32.u64 %0, t; }"
        : "=r"(a) : "l"(p));
    return a;
}

__device__ __forceinline__ void ldsm_x4(unsigned& r0, unsigned& r1,
                                        unsigned& r2, unsigned& r3, uint32_t addr) {
    asm volatile("ldmatrix.sync.aligned.m8n8.x4.shared.b16 {%0,%1,%2,%3}, [%4];"
                 : "=r"(r0), "=r"(r1), "=r"(r2), "=r"(r3) : "r"(addr));
}

__device__ __forceinline__ void mma16816(float* c, const unsigned* a, const unsigned* b) {
    asm volatile(
        "mma.sync.aligned.m16n8k16.row.col.f32.bf16.bf16.f32 "
        "{%0,%1,%2,%3},{%4,%5,%6,%7},{%8,%9},{%0,%1,%2,%3};\n"
        : "+f"(c[0]), "+f"(c[1]), "+f"(c[2]), "+f"(c[3])
        : "r"(a[0]), "r"(a[1]), "r"(a[2]), "r"(a[3]), "r"(b[0]), "r"(b[1]));
}

// ---------------------------------------------------------------------------
// Kernel 1: L2-normalize centroids -> fp32 + bf16 copies.
// ---------------------------------------------------------------------------
__global__ void normalize_centroids(const float* __restrict__ cent) {
    int row = blockIdx.x;
    int t   = threadIdx.x;  // 0..127
    float4 v = reinterpret_cast<const float4*>(cent + (size_t)row * ND)[t];
    float ss = v.x * v.x + v.y * v.y + v.z * v.z + v.w * v.w;
    #pragma unroll
    for (int o = 16; o > 0; o >>= 1) ss += __shfl_down_sync(0xffffffffu, ss, o);
    __shared__ float sred[4];
    if ((t & 31) == 0) sred[t >> 5] = ss;
    __syncthreads();
    float tot   = sred[0] + sred[1] + sred[2] + sred[3];
    float scale = 1.0f / fmaxf(sqrtf(tot), 1e-12f);
    float4 o4 = make_float4(v.x * scale, v.y * scale, v.z * scale, v.w * scale);
    reinterpret_cast<float4*>(g_cnorm + (size_t)row * ND)[t] = o4;
    __nv_bfloat162 p0 = __floats2bfloat162_rn(o4.x, o4.y);
    __nv_bfloat162 p1 = __floats2bfloat162_rn(o4.z, o4.w);
    uint2 pk = make_uint2(*reinterpret_cast<unsigned*>(&p0),
                          *reinterpret_cast<unsigned*>(&p1));
    reinterpret_cast<uint2*>(g_cnorm_bf)[(size_t)row * (ND / 4) + t] = pk;
}

// ---------------------------------------------------------------------------
// Kernel 1b: build fragment-native B layout (one 256B record = one warp
// B-fragment for an 8-col x 16-K subtile, lane-ordered).
// ---------------------------------------------------------------------------
__global__ void build_bfrag() {
    int r    = blockIdx.x * 8 + (threadIdx.x >> 5);  // record id 0..4095
    int lane = threadIdx.x & 31;
    int cb = r >> 5, kk = (r & 31) * 16;
    int n  = cb * 8 + (lane >> 2);
    int k0 = kk + (lane & 3) * 2;
    const unsigned* src = reinterpret_cast<const unsigned*>(g_cnorm_bf);
    unsigned x = src[(n * ND + k0) >> 1];
    unsigned y = src[(n * ND + k0 + 8) >> 1];
    g_bfrag[r * 32 + lane] = make_uint2(x, y);
}

// ---------------------------------------------------------------------------
// Kernel 2: fused GEMM-argmax. 512 threads (16 warps), CTA owns 128 rows.
//  - warp grid 4M x 4N, warp tile 32x32
//  - A resident in smem (LDSM), fragments SOFTWARE-PIPELINED (1 step ahead)
//  - B per-fragment coalesced LDG from g_bfrag, 2 steps ahead
//  - one-hot ZERO-FILL interleaved into the 8 epilogues (streaming stores,
//    overlapped with tensor work); final phase stores only the 1.0 per row
//  - per-n-tile atomicMax rowMax + margin candidates, exact fp32 refinement
// ---------------------------------------------------------------------------
#define ASTR 520        // bf16 elems per A row (512 + 8 pad)
#define OFF_STATM 0                          // rowMaxU: 128 u32
#define OFF_CNT   512                        // rowCnt:  128 int
#define OFF_CAND  1024                       // cand:    128*CAP ushort (4096B)
#define OFF_A     5120
#define SMEM_TOTAL (OFF_A + 128 * ASTR * 2)  // 138240

__global__ __launch_bounds__(512, 1) void fused_kernel(
    const float* __restrict__ q, const float* __restrict__ cent,
    float* __restrict__ out) {
    extern __shared__ char sm[];
    uint32_t sb = smem_u32(sm);
    unsigned*       rowMaxU = reinterpret_cast<unsigned*>(sm + OFF_STATM);
    int*            rowCnt  = reinterpret_cast<int*>(sm + OFF_CNT);
    unsigned short* cand    = reinterpret_cast<unsigned short*>(sm + OFF_CAND);
    __nv_bfloat16*  sA      = reinterpret_cast<__nv_bfloat16*>(sm + OFF_A);

    const unsigned FULL = 0xffffffffu;
    int tid  = threadIdx.x;
    int lane = tid & 31, wid = tid >> 5;
    int warpM = wid & 3, warpN = wid >> 2;   // 4M x 4N grid, warp tile 32x32
    int g = lane >> 2, tc = lane & 3;
    int m0 = blockIdx.x * 128;

    if (tid < 128) { rowMaxU[tid] = 0u; rowCnt[tid] = 0; }

    // ---- Load resident A tile: 128 x 512 fp32 -> bf16 ----
    const float4* q4 = reinterpret_cast<const float4*>(q);
    #pragma unroll 4
    for (int e = tid; e < 128 * 128; e += 512) {
        int row = e >> 7, c = e & 127;
        float4 v = q4[(size_t)(m0 + row) * 128 + c];
        __nv_bfloat162 p0 = __floats2bfloat162_rn(v.x, v.y);
        __nv_bfloat162 p1 = __floats2bfloat162_rn(v.z, v.w);
        uint2 pk = make_uint2(*reinterpret_cast<unsigned*>(&p0),
                              *reinterpret_cast<unsigned*>(&p1));
        *reinterpret_cast<uint2*>(&sA[row * ASTR + c * 4]) = pk;
    }

    float acc[2][4][4];
    #pragma unroll
    for (int mt = 0; mt < 2; mt++)
        #pragma unroll
        for (int s = 0; s < 4; s++)
            #pragma unroll
            for (int i = 0; i < 4; i++) acc[mt][s][i] = 0.0f;

    // B fragment prefetch (2 ahead), register ring of 4
    const uint2* bbase = g_bfrag + warpN * 4096 + lane;
    unsigned b[4][4][2];   // [slot][subtile][frag]
    auto loadB = [&](int slot, int cc) {
        int off = (cc >> 5) * 16384 + (cc & 31) * 32;
        #pragma unroll
        for (int s = 0; s < 4; s++) {
            uint2 v = __ldg(bbase + off + s * 1024);
            b[slot][s][0] = v.x; b[slot][s][1] = v.y;
        }
    };

    uint32_t aAddr = sb + OFF_A +
        ((warpM * 32 + (lane & 15)) * ASTR + ((lane >> 4) << 3)) * 2;

    // A fragment prefetch (1 ahead), double buffer
    unsigned a[2][2][4];   // [buf][mt][frag]
    auto loadA = [&](int buf, int cc) {
        int kb = (cc & 31) * 16;
        #pragma unroll
        for (int mt = 0; mt < 2; mt++)
            ldsm_x4(a[buf][mt][0], a[buf][mt][1], a[buf][mt][2], a[buf][mt][3],
                    aAddr + (mt * 16 * ASTR + kb) * 2);
    };

    loadB(0, 0);
    loadB(1, 1);
    __syncthreads();   // A visible, rowMax/cnt initialized
    loadA(0, 0);

    float* outHard = out + (size_t)NB * ND;
    float* outOH   = outHard + NB;

    // ---- Main loop: 256 steps = 8 n-tiles x 32 k-steps of 16 ----
    #pragma unroll 8
    for (int c = 0; c < 256; c++) {
        if (c + 2 < 256) loadB((c + 2) & 3, c + 2);
        if (c + 1 < 256) loadA((c + 1) & 1, c + 1);

        int buf = c & 1, sl = c & 3;
        #pragma unroll
        for (int mt = 0; mt < 2; mt++)
            #pragma unroll
            for (int s = 0; s < 4; s++)
                mma16816(acc[mt][s], a[buf][mt], b[sl][s]);

        if ((c & 31) == 31) {   // n-tile finished: argmax epilogue
            int n0 = (c >> 5) * 128;
            #pragma unroll
            for (int mt = 0; mt < 2; mt++) {
                float v0 = -3.4e38f, v1 = -3.4e38f;
                #pragma unroll
                for (int s = 0; s < 4; s++) {
                    v0 = fmaxf(v0, fmaxf(acc[mt][s][0], acc[mt][s][1]));
                    v1 = fmaxf(v1, fmaxf(acc[mt][s][2], acc[mt][s][3]));
                }
                v0 = fmaxf(v0, __shfl_xor_sync(FULL, v0, 1));
                v0 = fmaxf(v0, __shfl_xor_sync(FULL, v0, 2));
                v1 = fmaxf(v1, __shfl_xor_sync(FULL, v1, 1));
                v1 = fmaxf(v1, __shfl_xor_sync(FULL, v1, 2));
                if (tc == 0) {
                    int r = warpM * 32 + mt * 16 + g;
                    atomicMax(&rowMaxU[r], fmap(v0));
                    atomicMax(&rowMaxU[r + 8], fmap(v1));
                }
            }
            __syncthreads();   // all maxima for this tile published
            #pragma unroll
            for (int mt = 0; mt < 2; mt++) {
                int r0 = warpM * 32 + mt * 16 + g;
                float th0 = funmap(rowMaxU[r0]) - MARGIN;
                float th1 = funmap(rowMaxU[r0 + 8]) - MARGIN;
                #pragma unroll
                for (int s = 0; s < 4; s++) {
                    #pragma unroll
                    for (int i = 0; i < 4; i++) {
                        float v = acc[mt][s][i];
                        int   r = (i < 2) ? r0 : r0 + 8;
                        float th = (i < 2) ? th0 : th1;
                        if (v >= th) {
                            int p = atomicAdd(&rowCnt[r], 1);
                            if (p < CAP)
                                cand[r * CAP + p] = (unsigned short)
                                    (n0 + warpN * 32 + s * 8 + tc * 2 + (i & 1));
                        }
                        acc[mt][s][i] = 0.0f;
                    }
                }
            }
            // one-hot zero-fill for 16 rows (overlapped with next n-tile's
            // tensor work): rows [m0 + e*16, +16), e = tile index.
            {
                float4* ohb = reinterpret_cast<float4*>(
                    outOH + (size_t)(m0 + (c >> 5) * 16) * NP);
                float4 z = make_float4(0.f, 0.f, 0.f, 0.f);
                #pragma unroll
                for (int i = 0; i < 8; i++)
                    __stcs(ohb + tid + 512 * i, z);
            }
        }
    }
    __syncthreads();   // candidates complete; zero-fill ordered before 1.0s

    // ---- Refinement + output writes: warp w owns rows [w*8, w*8+8) ----
    const float4* c4n = reinterpret_cast<const float4*>(g_cnorm);
    const float4* ce4 = reinterpret_cast<const float4*>(cent);

    for (int rr = 0; rr < 8; rr++) {
        int r = wid * 8 + rr;
        int b2 = m0 + r;
        int cnt = rowCnt[r];
        int winner;
        if (cnt == 1) {
            winner = cand[r * CAP];
        } else {
            // exact fp32 dots; q row cached in registers
            float4 aq[4];
            const float4* qr = q4 + (size_t)b2 * 128;
            #pragma unroll
            for (int i = 0; i < 4; i++) aq[i] = qr[lane + 32 * i];
            float bv = -3.4e38f; int bi = NP;
            int lim = (cnt <= CAP) ? cnt : NP;   // overflow -> full exact scan
            for (int j = 0; j < lim; j++) {
                int col = (cnt <= CAP) ? (int)cand[r * CAP + j] : j;
                const float4* cr = c4n + (size_t)col * 128;
                float s = 0.0f;
                #pragma unroll
                for (int i = 0; i < 4; i++) {
                    float4 cc = cr[lane + 32 * i];
                    s = fmaf(aq[i].x, cc.x, fmaf(aq[i].y, cc.y,
                        fmaf(aq[i].z, cc.z, fmaf(aq[i].w, cc.w, s))));
                }
                #pragma unroll
                for (int o = 16; o > 0; o >>= 1)
                    s += __shfl_xor_sync(FULL, s, o);
                if (s > bv || (s == bv && col < bi)) { bv = s; bi = col; }
            }
            winner = bi;
        }

        // context gather (raw centroids)
        float4* ctx = reinterpret_cast<float4*>(out + (size_t)b2 * ND);
        #pragma unroll
        for (int i = 0; i < 4; i++)
            ctx[lane + 32 * i] = ce4[(size_t)winner * 128 + lane + 32 * i];
        if (lane == 0) {
            outHard[b2] = (float)winner;
            outOH[(size_t)b2 * NP + winner] = 1.0f;   // zeros already streamed
        }
    }
}

// ---------------------------------------------------------------------------
// Launch: out = [context (B*D) | hard (B) | routing (B*P)] as float32
// ---------------------------------------------------------------------------
extern "C" void kernel_launch(void* const* d_in, const int* in_sizes, int n_in,
                              void* d_out, int out_size) {
    const float* q    = (const float*)d_in[0];  // (B, D) fp32
    const float* cent = (const float*)d_in[1];  // (P, D) fp32
    float* out = (float*)d_out;

    cudaFuncSetAttribute(fused_kernel,
                         cudaFuncAttributeMaxDynamicSharedMemorySize, SMEM_TOTAL);
    normalize_centroids<<<NP, 128>>>(cent);
    build_bfrag<<<512, 256>>>();
    fused_kernel<<<NB / 128, 512, SMEM_TOTAL>>>(q, cent, out);
}